// round 2
// baseline (speedup 1.0000x reference)
#include <cuda_runtime.h>
#include <cuda_bf16.h>

// CRF negative log-likelihood, fixed shapes.
#define B_ 256
#define S_ 1024
#define T_ 64
#define PF 8   // emission prefetch depth

__device__ float g_diff[B_];

// One block per batch element, one thread per tag.
__global__ void __launch_bounds__(T_) crf_forward_kernel(
    const float* __restrict__ emissions,   // (B, S, T)
    const int* __restrict__ tags,          // (B, S) int32 (JAX x64 disabled)
    const float* __restrict__ trans,       // (T, T)
    const float* __restrict__ startT,      // (T,)
    const float* __restrict__ endT)        // (T,)
{
    const int b = blockIdx.x;
    const int j = threadIdx.x;

    __shared__ __align__(16) float u[2][T_];
    __shared__ float rsh[2];
    __shared__ float redA[T_];
    __shared__ float redB[T_];

    // Per-thread column of E = exp(trans): constant across all steps.
    float Ecol[T_];
#pragma unroll
    for (int i = 0; i < T_; ++i)
        Ecol[i] = __expf(__ldg(trans + i * T_ + j));

    const float* emb = emissions + (size_t)b * S_ * T_ + j;

    // t = 0: v0_j = exp(start_j + em0_j)
    float v = __expf(__ldg(startT + j) + __ldg(emb));
    u[0][j] = v;
    if (j == 0) rsh[0] = __frcp_rn(v);
    double c = 0.0;   // running log-scale, thread 0 only

    // Prefetch ring for emissions (em[t] for t = 1..PF)
    float pf[PF];
#pragma unroll
    for (int k = 0; k < PF; ++k)
        pf[k] = __ldg(emb + (size_t)(1 + k) * T_);

    __syncthreads();

    int cur = 0;
    int t = 1;

    // Main loop: 127 chunks of 8 (t = 1..1016), then 7 remainder steps.
#pragma unroll 1
    for (int tb = 0; tb < 127; ++tb) {
#pragma unroll
        for (int k = 0; k < 8; ++k, ++t) {
            float em_t = pf[k];
            if (t + PF < S_)
                pf[k] = __ldg(emb + (size_t)(t + PF) * T_);

            float r = rsh[cur];
            if (j == 0) c += (double)__logf(v);   // v = v_{t-1, 0} on thread 0

            float a0 = 0.f, a1 = 0.f, a2 = 0.f, a3 = 0.f;
            const float4* u4 = reinterpret_cast<const float4*>(u[cur]);
#pragma unroll
            for (int i = 0; i < T_ / 4; ++i) {
                float4 uu = u4[i];
                a0 = fmaf(uu.x, Ecol[4 * i + 0], a0);
                a1 = fmaf(uu.y, Ecol[4 * i + 1], a1);
                a2 = fmaf(uu.z, Ecol[4 * i + 2], a2);
                a3 = fmaf(uu.w, Ecol[4 * i + 3], a3);
            }
            float s = (a0 + a1) + (a2 + a3);
            v = s * r * __expf(em_t);

            int nxt = cur ^ 1;
            u[nxt][j] = v;
            if (j == 0) rsh[nxt] = __frcp_rn(v);
            cur = nxt;
            __syncthreads();
        }
    }
    // remainder: t = 1017..1023 (7 steps), emissions already in pf[0..6]
#pragma unroll
    for (int k = 0; k < 7; ++k, ++t) {
        float em_t = pf[k];
        float r = rsh[cur];
        if (j == 0) c += (double)__logf(v);

        float a0 = 0.f, a1 = 0.f, a2 = 0.f, a3 = 0.f;
        const float4* u4 = reinterpret_cast<const float4*>(u[cur]);
#pragma unroll
        for (int i = 0; i < T_ / 4; ++i) {
            float4 uu = u4[i];
            a0 = fmaf(uu.x, Ecol[4 * i + 0], a0);
            a1 = fmaf(uu.y, Ecol[4 * i + 1], a1);
            a2 = fmaf(uu.z, Ecol[4 * i + 2], a2);
            a3 = fmaf(uu.w, Ecol[4 * i + 3], a3);
        }
        float s = (a0 + a1) + (a2 + a3);
        v = s * r * __expf(em_t);

        int nxt = cur ^ 1;
        u[nxt][j] = v;
        if (j == 0) rsh[nxt] = __frcp_rn(v);
        cur = nxt;
        __syncthreads();
    }

    // Final logsumexp with end transitions: partition = c + log(sum_j v_j * exp(end_j))
    redA[j] = v * __expf(__ldg(endT + j));
    __syncthreads();

    // Score of the gold path, parallel over time steps.
    float sc = 0.f;
    const int* tg = tags + (size_t)b * S_;
    const float* emB = emissions + (size_t)b * S_ * T_;
#pragma unroll 4
    for (int tt = j; tt < S_; tt += T_) {
        int tag = tg[tt];
        sc += __ldg(emB + (size_t)tt * T_ + tag);
        if (tt + 1 < S_) {
            int tag2 = tg[tt + 1];
            sc += __ldg(trans + tag * T_ + tag2);
        }
    }
    if (j == 0) {
        sc += __ldg(startT + tg[0]);
        sc += __ldg(endT + tg[S_ - 1]);
    }
    redB[j] = sc;
    __syncthreads();

    if (j == 0) {
        float sumw = 0.f;
        float sums = 0.f;
#pragma unroll
        for (int i = 0; i < T_; ++i) {
            sumw += redA[i];
            sums += redB[i];
        }
        double partition = c + (double)__logf(sumw);
        g_diff[b] = (float)(partition - (double)sums);
    }
}

__global__ void crf_reduce_kernel(float* __restrict__ out)
{
    __shared__ float sh[B_];
    int t = threadIdx.x;
    sh[t] = g_diff[t];
    __syncthreads();
#pragma unroll
    for (int off = B_ / 2; off > 0; off >>= 1) {
        if (t < off) sh[t] += sh[t + off];
        __syncthreads();
    }
    if (t == 0) out[0] = sh[0] / (float)B_;
}

extern "C" void kernel_launch(void* const* d_in, const int* in_sizes, int n_in,
                              void* d_out, int out_size)
{
    const float* emissions = (const float*)d_in[0];
    const int*   tags      = (const int*)d_in[1];
    const float* trans     = (const float*)d_in[2];
    const float* startT    = (const float*)d_in[3];
    const float* endT      = (const float*)d_in[4];
    float* out = (float*)d_out;

    crf_forward_kernel<<<B_, T_>>>(emissions, tags, trans, startT, endT);
    crf_reduce_kernel<<<1, B_>>>(out);
}

// round 3
// speedup vs baseline: 1.3895x; 1.3895x over previous
#include <cuda_runtime.h>
#include <cuda_bf16.h>

// CRF negative log-likelihood, fixed shapes.
#define B_ 256
#define S_ 1024
#define T_ 64
#define PF 8   // emission prefetch depth (ring), renorm every 4 steps

__device__ float g_diff[B_];

// 2 batch elements per block: threads [0,64) -> batch 2*bid, [64,128) -> 2*bid+1.
// Warps 0..3 occupy all 4 SMSPs.
__global__ void __launch_bounds__(2 * T_) crf_forward_kernel(
    const float* __restrict__ emissions,   // (B, S, T)
    const int* __restrict__ tags,          // (B, S) int32
    const float* __restrict__ trans,       // (T, T)
    const float* __restrict__ startT,      // (T,)
    const float* __restrict__ endT)        // (T,)
{
    const int tid  = threadIdx.x;
    const int half = tid >> 6;           // which batch element in this block
    const int j    = tid & 63;           // tag index
    const int b    = 2 * blockIdx.x + half;

    __shared__ __align__(16) float u[2][2][T_];   // [buf][half][tag]
    __shared__ float redA[2][T_];
    __shared__ float redB[2][T_];

    // Per-thread column of E = exp(trans): constant across all steps.
    float Ecol[T_];
#pragma unroll
    for (int i = 0; i < T_; ++i)
        Ecol[i] = __expf(__ldg(trans + i * T_ + j));

    const float* emb = emissions + (size_t)b * S_ * T_ + j;

    // t = 0: u0_j = exp(start_j + em0_j)
    float v = __expf(__ldg(startT + j) + __ldg(emb));
    u[0][half][j] = v;
    double c = 0.0;   // running log-scale (accumulated on thread j==0 of each half)

    // Prefetch ring for emissions (em[t] for t = 1..PF)
    float pf[PF];
#pragma unroll
    for (int k = 0; k < PF; ++k)
        pf[k] = __ldg(emb + (size_t)(1 + k) * T_);

    __syncthreads();

    int cur = 0;
    int t = 1;

    // Helper macro-free structure: 127 chunks of 8 steps (t=1..1016), then 7
    // remainder. Renormalize (divide by u[...][0], log it) on k==0 and k==4.
#pragma unroll 1
    for (int tb = 0; tb < 127; ++tb) {
#pragma unroll
        for (int k = 0; k < 8; ++k, ++t) {
            float em_t = pf[k];
            if (t + PF < S_)
                pf[k] = __ldg(emb + (size_t)(t + PF) * T_);

            const float* ub = u[cur][half];

            float scale_mul = __expf(em_t);
            if ((k & 3) == 0) {
                float scale = ub[0];            // broadcast LDS
                if (j == 0) c += (double)__logf(scale);
                scale_mul *= __frcp_rn(scale);  // fold renorm into emission factor
            }

            float a0 = 0.f, a1 = 0.f, a2 = 0.f, a3 = 0.f;
            const float4* u4 = reinterpret_cast<const float4*>(ub);
#pragma unroll
            for (int i = 0; i < T_ / 4; ++i) {
                float4 uu = u4[i];
                a0 = fmaf(uu.x, Ecol[4 * i + 0], a0);
                a1 = fmaf(uu.y, Ecol[4 * i + 1], a1);
                a2 = fmaf(uu.z, Ecol[4 * i + 2], a2);
                a3 = fmaf(uu.w, Ecol[4 * i + 3], a3);
            }
            float s = (a0 + a1) + (a2 + a3);
            v = s * scale_mul;

            cur ^= 1;
            u[cur][half][j] = v;
            __syncthreads();
        }
    }
    // remainder: t = 1017..1023 (7 steps)
#pragma unroll
    for (int k = 0; k < 7; ++k, ++t) {
        float em_t = pf[k];
        const float* ub = u[cur][half];

        float scale_mul = __expf(em_t);
        if ((k & 3) == 0) {
            float scale = ub[0];
            if (j == 0) c += (double)__logf(scale);
            scale_mul *= __frcp_rn(scale);
        }

        float a0 = 0.f, a1 = 0.f, a2 = 0.f, a3 = 0.f;
        const float4* u4 = reinterpret_cast<const float4*>(ub);
#pragma unroll
        for (int i = 0; i < T_ / 4; ++i) {
            float4 uu = u4[i];
            a0 = fmaf(uu.x, Ecol[4 * i + 0], a0);
            a1 = fmaf(uu.y, Ecol[4 * i + 1], a1);
            a2 = fmaf(uu.z, Ecol[4 * i + 2], a2);
            a3 = fmaf(uu.w, Ecol[4 * i + 3], a3);
        }
        float s = (a0 + a1) + (a2 + a3);
        v = s * scale_mul;

        cur ^= 1;
        u[cur][half][j] = v;
        __syncthreads();
    }

    // Final logsumexp with end transitions:
    // partition = c + log(sum_j u_j * exp(end_j))
    redA[half][j] = v * __expf(__ldg(endT + j));

    // Score of the gold path, parallel over time steps (64 threads per half).
    float sc = 0.f;
    const int* tg = tags + (size_t)b * S_;
    const float* emB = emissions + (size_t)b * S_ * T_;
#pragma unroll 4
    for (int tt = j; tt < S_; tt += T_) {
        int tag = tg[tt];
        sc += __ldg(emB + (size_t)tt * T_ + tag);
        if (tt + 1 < S_) {
            int tag2 = tg[tt + 1];
            sc += __ldg(trans + tag * T_ + tag2);
        }
    }
    if (j == 0) {
        sc += __ldg(startT + tg[0]);
        sc += __ldg(endT + tg[S_ - 1]);
    }
    redB[half][j] = sc;
    __syncthreads();

    if (j == 0) {
        float sumw = 0.f;
        float sums = 0.f;
#pragma unroll
        for (int i = 0; i < T_; ++i) {
            sumw += redA[half][i];
            sums += redB[half][i];
        }
        double partition = c + (double)__logf(sumw);
        g_diff[b] = (float)(partition - (double)sums);
    }
}

__global__ void crf_reduce_kernel(float* __restrict__ out)
{
    __shared__ float sh[B_];
    int t = threadIdx.x;
    sh[t] = g_diff[t];
    __syncthreads();
#pragma unroll
    for (int off = B_ / 2; off > 0; off >>= 1) {
        if (t < off) sh[t] += sh[t + off];
        __syncthreads();
    }
    if (t == 0) out[0] = sh[0] / (float)B_;
}

extern "C" void kernel_launch(void* const* d_in, const int* in_sizes, int n_in,
                              void* d_out, int out_size)
{
    const float* emissions = (const float*)d_in[0];
    const int*   tags      = (const int*)d_in[1];
    const float* trans     = (const float*)d_in[2];
    const float* startT    = (const float*)d_in[3];
    const float* endT      = (const float*)d_in[4];
    float* out = (float*)d_out;

    crf_forward_kernel<<<B_ / 2, 2 * T_>>>(emissions, tags, trans, startT, endT);
    crf_reduce_kernel<<<1, B_>>>(out);
}